// round 9
// baseline (speedup 1.0000x reference)
#include <cuda_runtime.h>
#include <cuda_bf16.h>

#define N_GROUPS 256
#define EMBED 1024
#define VEC4 (EMBED / 4)   // 256 float4 per row
#define KSPLIT 8
#define NPART (N_GROUPS * N_GROUPS)   // 65536
#define CHUNK 16
#define NCHUNK 256
#define LOSS_BLOCKS 128

// Scratch (device globals; no allocation allowed)
__device__ float g_im_mean[N_GROUPS * EMBED];
__device__ float g_s_mean[N_GROUPS * EMBED];
__device__ float g_part[2 * N_GROUPS * 3 * EMBED];   // [src][group][slot][1024]
__device__ float g_Spart[KSPLIT * NPART];
__device__ float g_loss_part[LOSS_BLOCKS];
__device__ int   g_count;            // zero at load; reset by last block each launch
__device__ int   g_gstart[2 * N_GROUPS];
__device__ int   g_total[2];
__device__ int4  g_cmeta[2 * NCHUNK];   // {g0, e0, e1, slot0} per chunk

// ---------------------------------------------------------------------------
// Kernel 0: metadata. 1 block x 256 threads.
// For each source: inclusive prefix of counts, group starts, total, and
// per-chunk classification metadata (first group, its end, next end, slot).
// ---------------------------------------------------------------------------
__global__ void __launch_bounds__(256) meta_kernel(
    const int* __restrict__ num_clips, const int* __restrict__ num_caps)
{
    __shared__ int cs[N_GROUPS];
    __shared__ int pref[N_GROUPS];
    __shared__ int wsum[8];
    const int t = threadIdx.x;

    for (int srcI = 0; srcI < 2; srcI++) {
        const int* __restrict__ cnt = (srcI == 0) ? num_clips : num_caps;
        int c = cnt[t];
        cs[t] = c;
        // warp-inclusive scan + warp offsets
        int incl = c;
        #pragma unroll
        for (int o = 1; o < 32; o <<= 1) {
            int v = __shfl_up_sync(0xFFFFFFFFu, incl, o);
            if ((t & 31) >= o) incl += v;
        }
        if ((t & 31) == 31) wsum[t >> 5] = incl;
        __syncthreads();
        int base = 0;
        #pragma unroll
        for (int w = 0; w < 8; w++) base += (w < (t >> 5)) ? wsum[w] : 0;
        const int p = incl + base;
        pref[t] = p;
        g_gstart[srcI * N_GROUPS + t] = p - c;
        if (t == N_GROUPS - 1) g_total[srcI] = p;
        __syncthreads();

        // per-chunk metadata (thread t = chunk t)
        const int total = pref[N_GROUPS - 1];
        const int rbeg = t * CHUNK;
        int4 m;
        if (rbeg < total) {
            int lo = 0, hi = N_GROUPS - 1;
            while (lo < hi) {
                int mid = (lo + hi) >> 1;
                if (pref[mid] > rbeg) hi = mid; else lo = mid + 1;
            }
            const int g0 = lo;
            const int e0 = pref[g0];
            const int e1 = (g0 + 1 < N_GROUPS) ? pref[g0 + 1] : 0x7FFFFFFF;
            const int slot0 = t - ((e0 - cs[g0]) >> 4);
            m = make_int4(g0, e0, e1, slot0);
        } else {
            m = make_int4(0, 0x7FFFFFFF, 0x7FFFFFFF, 0);
        }
        g_cmeta[srcI * NCHUNK + t] = m;
        __syncthreads();   // smem reuse barrier for next source
    }
}

// ---------------------------------------------------------------------------
// Kernel 1: balanced chunked segment-sum. 1024 blocks x 128 threads.
// blockIdx.x = c*4 + src*2 + half. Every block: exactly 16 rows (last chunk:
// remainder) of one half-row. Rows classified into <=3 group segments using
// precomputed chunk metadata; partials to g_part[(src,g,slot)].
// ---------------------------------------------------------------------------
__global__ void __launch_bounds__(128) segchunk_kernel(
    const float* __restrict__ im, const float* __restrict__ s)
{
    const int b = blockIdx.x;
    const int c = b >> 2;
    const int srcI = (b >> 1) & 1;
    const int half = b & 1;
    const float4* __restrict__ src = (const float4*)((srcI == 0) ? im : s);

    const int total = g_total[srcI];
    const int rbeg = c * CHUNK;
    if (rbeg >= total) return;
    const int rend = min(rbeg + CHUNK, total);
    const int nrows = rend - rbeg;

    const int4 m = g_cmeta[srcI * NCHUNK + c];
    const int g0 = m.x, e0 = m.y, e1 = m.z, slot0 = m.w;

    const int t = threadIdx.x;
    const float4* p = src + (size_t)rbeg * VEC4 + half * 128 + t;

    float4 a0 = make_float4(0.f, 0.f, 0.f, 0.f);
    float4 a1 = make_float4(0.f, 0.f, 0.f, 0.f);
    float4 a2 = make_float4(0.f, 0.f, 0.f, 0.f);

    int r = 0;
    for (; r + 8 <= nrows; r += 8) {
        float4 x[8];
        #pragma unroll
        for (int u = 0; u < 8; u++) x[u] = p[(size_t)(r + u) * VEC4];
        #pragma unroll
        for (int u = 0; u < 8; u++) {
            const int row = rbeg + r + u;
            if (row < e0)      { a0.x += x[u].x; a0.y += x[u].y; a0.z += x[u].z; a0.w += x[u].w; }
            else if (row < e1) { a1.x += x[u].x; a1.y += x[u].y; a1.z += x[u].z; a1.w += x[u].w; }
            else               { a2.x += x[u].x; a2.y += x[u].y; a2.z += x[u].z; a2.w += x[u].w; }
        }
    }
    for (; r < nrows; r++) {
        float4 x = p[(size_t)r * VEC4];
        const int row = rbeg + r;
        if (row < e0)      { a0.x += x.x; a0.y += x.y; a0.z += x.z; a0.w += x.w; }
        else if (row < e1) { a1.x += x.x; a1.y += x.y; a1.z += x.z; a1.w += x.w; }
        else               { a2.x += x.x; a2.y += x.y; a2.z += x.z; a2.w += x.w; }
    }

    const int col4 = half * 128 + t;
    {
        float4* w = (float4*)&g_part[(size_t)((srcI * N_GROUPS + g0) * 3 + slot0) * EMBED];
        w[col4] = a0;
    }
    if (e0 < rend) {  // group g0+1 starts inside this chunk -> its slot 0
        float4* w = (float4*)&g_part[(size_t)((srcI * N_GROUPS + g0 + 1) * 3 + 0) * EMBED];
        w[col4] = a1;
    }
    if (e1 < rend) {
        float4* w = (float4*)&g_part[(size_t)((srcI * N_GROUPS + g0 + 2) * 3 + 0) * EMBED];
        w[col4] = a2;
    }
}

// ---------------------------------------------------------------------------
// Kernel 2: combine chunk partials -> group means. 512 blocks x 256 threads.
// ---------------------------------------------------------------------------
__global__ void __launch_bounds__(256) combine_kernel(
    const int* __restrict__ num_clips, const int* __restrict__ num_caps)
{
    const int b = blockIdx.x;
    const int g = b >> 1;
    const int srcI = b & 1;
    const int* __restrict__ cnt = (srcI == 0) ? num_clips : num_caps;
    float* __restrict__ dst = (srcI == 0) ? g_im_mean : g_s_mean;
    const int t = threadIdx.x;

    const int n = cnt[g];
    const int start = g_gstart[srcI * N_GROUPS + g];
    const float inv = 1.0f / (float)n;
    const int nslots = ((start + n - 1) >> 4) - (start >> 4) + 1;   // 1..3

    const float4* basep = (const float4*)&g_part[(size_t)((srcI * N_GROUPS + g) * 3) * EMBED];
    float4 v = basep[t];
    if (nslots > 1) {
        float4 p1 = basep[VEC4 + t];
        v.x += p1.x; v.y += p1.y; v.z += p1.z; v.w += p1.w;
    }
    if (nslots > 2) {
        float4 p2 = basep[2 * VEC4 + t];
        v.x += p2.x; v.y += p2.y; v.z += p2.z; v.w += p2.w;
    }
    float4 o4;
    o4.x = v.x * inv; o4.y = v.y * inv; o4.z = v.z * inv; o4.w = v.w * inv;
    ((float4*)dst)[(size_t)g * VEC4 + t] = o4;
}

// ---------------------------------------------------------------------------
// Kernel 3: K-split GEMM partials, double-buffered smem. (unchanged)
// ---------------------------------------------------------------------------
__global__ void __launch_bounds__(256) gemm_partial_kernel()
{
    __shared__ float As[2][16][68];
    __shared__ float Bs[2][16][68];

    const int tid = threadIdx.x;
    const int tx = tid & 15;
    const int ty = tid >> 4;
    const int bi = blockIdx.y * 64;
    const int bj = blockIdx.x * 64;
    const int kbase = blockIdx.z * (EMBED / KSPLIT);

    const int lr = tid >> 2;
    const int lc = tid & 3;

    const float* Abase = &g_im_mean[(size_t)(bi + lr) * EMBED + kbase + lc * 4];
    const float* Bbase = &g_s_mean [(size_t)(bj + lr) * EMBED + kbase + lc * 4];

    float acc[4][4] = {};

    float4 a  = *(const float4*)Abase;
    float4 bv = *(const float4*)Bbase;
    As[0][lc * 4 + 0][lr] = a.x;  As[0][lc * 4 + 1][lr] = a.y;
    As[0][lc * 4 + 2][lr] = a.z;  As[0][lc * 4 + 3][lr] = a.w;
    Bs[0][lc * 4 + 0][lr] = bv.x; Bs[0][lc * 4 + 1][lr] = bv.y;
    Bs[0][lc * 4 + 2][lr] = bv.z; Bs[0][lc * 4 + 3][lr] = bv.w;
    __syncthreads();

    #pragma unroll
    for (int c = 0; c < 8; c++) {
        float4 an, bn;
        if (c < 7) {
            an = *(const float4*)(Abase + (c + 1) * 16);
            bn = *(const float4*)(Bbase + (c + 1) * 16);
        }
        const int cur = c & 1;
        #pragma unroll
        for (int kk = 0; kk < 16; kk++) {
            float4 av = *(const float4*)&As[cur][kk][ty * 4];
            float4 bw = *(const float4*)&Bs[cur][kk][tx * 4];
            acc[0][0] += av.x * bw.x; acc[0][1] += av.x * bw.y;
            acc[0][2] += av.x * bw.z; acc[0][3] += av.x * bw.w;
            acc[1][0] += av.y * bw.x; acc[1][1] += av.y * bw.y;
            acc[1][2] += av.y * bw.z; acc[1][3] += av.y * bw.w;
            acc[2][0] += av.z * bw.x; acc[2][1] += av.z * bw.y;
            acc[2][2] += av.z * bw.z; acc[2][3] += av.z * bw.w;
            acc[3][0] += av.w * bw.x; acc[3][1] += av.w * bw.y;
            acc[3][2] += av.w * bw.z; acc[3][3] += av.w * bw.w;
        }
        if (c < 7) {
            const int nb = (c + 1) & 1;
            As[nb][lc * 4 + 0][lr] = an.x;  As[nb][lc * 4 + 1][lr] = an.y;
            As[nb][lc * 4 + 2][lr] = an.z;  As[nb][lc * 4 + 3][lr] = an.w;
            Bs[nb][lc * 4 + 0][lr] = bn.x;  Bs[nb][lc * 4 + 1][lr] = bn.y;
            Bs[nb][lc * 4 + 2][lr] = bn.z;  Bs[nb][lc * 4 + 3][lr] = bn.w;
            __syncthreads();
        }
    }

    float* outp = g_Spart + (size_t)blockIdx.z * NPART;
    #pragma unroll
    for (int i = 0; i < 4; i++) {
        float4 v;
        v.x = acc[i][0]; v.y = acc[i][1]; v.z = acc[i][2]; v.w = acc[i][3];
        *(float4*)&outp[(size_t)(bi + ty * 4 + i) * N_GROUPS + bj + tx * 4] = v;
    }
}

// ---------------------------------------------------------------------------
// Kernel 4: fused K-split reduce + diag + hinge loss.
// 128 blocks x 128 threads; last-block-arrival final reduction (fixed order).
// ---------------------------------------------------------------------------
__global__ void __launch_bounds__(128) fused_loss_kernel(float* __restrict__ out)
{
    __shared__ float diag_s[N_GROUPS];
    __shared__ float red[4];
    __shared__ int is_last;

    const int t = threadIdx.x;
    const int b = blockIdx.x;

    #pragma unroll
    for (int u = 0; u < 2; u++) {
        const int idx = t + u * 128;
        float d = 0.f;
        #pragma unroll
        for (int z = 0; z < KSPLIT; z++)
            d += g_Spart[(size_t)z * NPART + idx * (N_GROUPS + 1)];
        diag_s[idx] = d;
    }
    __syncthreads();

    const int q = b * 128 + t;          // 0..16383
    float4 v = make_float4(0.f, 0.f, 0.f, 0.f);
    #pragma unroll
    for (int z = 0; z < KSPLIT; z++) {
        float4 p = *(const float4*)&g_Spart[(size_t)z * NPART + q * 4];
        v.x += p.x; v.y += p.y; v.z += p.z; v.w += p.w;
    }

    const int i = q >> 6;
    const int j0 = (q & 63) * 4;
    const float di = diag_s[i];
    float vv[4] = {v.x, v.y, v.z, v.w};
    float sum = 0.f;
    #pragma unroll
    for (int c = 0; c < 4; c++) {
        const int j = j0 + c;
        if (j != i)
            sum += fmaxf(vv[c] - di, 0.f) + fmaxf(vv[c] - diag_s[j], 0.f);
    }

    #pragma unroll
    for (int o = 16; o; o >>= 1) sum += __shfl_xor_sync(0xFFFFFFFFu, sum, o);
    if ((t & 31) == 0) red[t >> 5] = sum;
    __syncthreads();

    if (t == 0) {
        g_loss_part[b] = red[0] + red[1] + red[2] + red[3];
        __threadfence();
        int old = atomicAdd(&g_count, 1);
        is_last = (old == LOSS_BLOCKS - 1) ? 1 : 0;
    }
    __syncthreads();

    if (is_last) {
        float v2 = __ldcg(&g_loss_part[t]);
        #pragma unroll
        for (int o = 16; o; o >>= 1) v2 += __shfl_xor_sync(0xFFFFFFFFu, v2, o);
        if ((t & 31) == 0) red[t >> 5] = v2;
        __syncthreads();
        if (t == 0) {
            out[0] = red[0] + red[1] + red[2] + red[3];
            g_count = 0;                 // reset for next replay
        }
    }
}

extern "C" void kernel_launch(void* const* d_in, const int* in_sizes, int n_in,
                              void* d_out, int out_size)
{
    const float* im        = (const float*)d_in[0];
    const float* s         = (const float*)d_in[1];
    const int*   num_clips = (const int*)d_in[2];
    const int*   num_caps  = (const int*)d_in[3];
    float* out = (float*)d_out;

    meta_kernel<<<1, 256>>>(num_clips, num_caps);
    segchunk_kernel<<<NCHUNK * 4, 128>>>(im, s);
    combine_kernel<<<N_GROUPS * 2, 256>>>(num_clips, num_caps);
    gemm_partial_kernel<<<dim3(4, 4, KSPLIT), 256>>>();
    fused_loss_kernel<<<LOSS_BLOCKS, 128>>>(out);
}